// round 15
// baseline (speedup 1.0000x reference)
#include <cuda_runtime.h>
#include <math.h>
#include <stdint.h>

#define TT 512
#define BB 64
#define HH 1024
#define NCTA 128
#define NTHR 512

typedef unsigned long long u64;

__device__ __align__(256) float g_pre[(size_t)TT * HH * BB];  // [t][j][b]
__device__ __align__(256) float g_h0[2][HH * BB];             // [k][b]; H0[t] in g_h0[t&1]
__device__ __align__(256) float g_h1[2][HH * BB];             // H1[t] in g_h1[t&1]
__device__ u64 g_arrive;
__device__ volatile u64 g_release;

__device__ __forceinline__ void ffma2(u64& d, u64 a, u64 b)
{ asm("fma.rn.f32x2 %0,%1,%2,%0;" : "+l"(d) : "l"(a), "l"(b)); }
__device__ __forceinline__ void fadd2(u64& d, u64 a)
{ asm("add.rn.f32x2 %0,%0,%1;" : "+l"(d) : "l"(a)); }
__device__ __forceinline__ u64 dup2(float x)
{ u64 r; asm("mov.b64 %0,{%1,%1};" : "=l"(r) : "f"(x)); return r; }
__device__ __forceinline__ void unpack2(u64 s, float& lo, float& hi)
{ asm("mov.b64 {%0,%1},%2;" : "=f"(lo), "=f"(hi) : "l"(s)); }

// Split ticket barrier (monotonic across graph replays; 1 CTA/SM, all resident)
__device__ __forceinline__ void bar_arrive(u64& tkt)
{
    __syncthreads();
    if (threadIdx.x == 0) {
        __threadfence();
        u64 old = atomicAdd(&g_arrive, 1ULL);
        tkt = old / NCTA + 1ULL;
        if ((old % NCTA) == (NCTA - 1)) { __threadfence(); g_release = tkt; }
    }
}
__device__ __forceinline__ void bar_wait(u64 tkt)
{
    if (threadIdx.x == 0) {
        while (g_release < tkt) {}
        __threadfence();
    }
    __syncthreads();
}

// ---------------------------------------------------------------------------
// pregemm (FFMA2): g_pre[t][j][b] = x[t][b]·Wih0[j] + bih0[j] + bhh0[j]
// ---------------------------------------------------------------------------
__global__ void __launch_bounds__(256) pregemm(const float* __restrict__ X,
                                               const float* __restrict__ W,
                                               const float* __restrict__ bih,
                                               const float* __restrict__ bhh)
{
    __shared__ float As[16][132];  // [k][m]
    __shared__ float Bs[16][68];   // [k][n]
    const int tid = threadIdx.x;
    const int m0 = blockIdx.y * 128;
    const int n0 = blockIdx.x * 64;
    const int tx = tid & 15;
    const int ty = tid >> 4;

    u64 acc[4][4];
#pragma unroll
    for (int i = 0; i < 4; i++)
#pragma unroll
        for (int j = 0; j < 4; j++) acc[i][j] = 0ULL;

    for (int k0 = 0; k0 < 1024; k0 += 16) {
#pragma unroll
        for (int i = 0; i < 2; i++) {
            int q = tid + i * 256;
            int m = q >> 2, kq = (q & 3) << 2;
            float4 v = __ldg((const float4*)&X[(size_t)(m0 + m) * 1024 + k0 + kq]);
            As[kq + 0][m] = v.x; As[kq + 1][m] = v.y;
            As[kq + 2][m] = v.z; As[kq + 3][m] = v.w;
        }
        {
            int n = tid >> 2, kq = (tid & 3) << 2;
            float4 v = __ldg((const float4*)&W[(size_t)(n0 + n) * 1024 + k0 + kq]);
            Bs[kq + 0][n] = v.x; Bs[kq + 1][n] = v.y;
            Bs[kq + 2][n] = v.z; Bs[kq + 3][n] = v.w;
        }
        __syncthreads();
#pragma unroll
        for (int kk = 0; kk < 16; kk++) {
            ulonglong2 a01 = *(const ulonglong2*)&As[kk][ty * 8];
            ulonglong2 a23 = *(const ulonglong2*)&As[kk][ty * 8 + 4];
            float4 bv = *(const float4*)&Bs[kk][tx * 4];
            u64 bd0 = dup2(bv.x), bd1 = dup2(bv.y), bd2 = dup2(bv.z), bd3 = dup2(bv.w);
            ffma2(acc[0][0], a01.x, bd0); ffma2(acc[0][1], a01.x, bd1);
            ffma2(acc[0][2], a01.x, bd2); ffma2(acc[0][3], a01.x, bd3);
            ffma2(acc[1][0], a01.y, bd0); ffma2(acc[1][1], a01.y, bd1);
            ffma2(acc[1][2], a01.y, bd2); ffma2(acc[1][3], a01.y, bd3);
            ffma2(acc[2][0], a23.x, bd0); ffma2(acc[2][1], a23.x, bd1);
            ffma2(acc[2][2], a23.x, bd2); ffma2(acc[2][3], a23.x, bd3);
            ffma2(acc[3][0], a23.y, bd0); ffma2(acc[3][1], a23.y, bd1);
            ffma2(acc[3][2], a23.y, bd2); ffma2(acc[3][3], a23.y, bd3);
        }
        __syncthreads();
    }

#pragma unroll
    for (int ip = 0; ip < 4; ip++) {
        int m = m0 + ty * 8 + 2 * ip;
        int t = m >> 6, b = m & 63;
#pragma unroll
        for (int j = 0; j < 4; j++) {
            int gn = n0 + tx * 4 + j;
            u64 bias = dup2(__ldg(&bih[gn]) + __ldg(&bhh[gn]));
            fadd2(acc[ip][j], bias);
            *(u64*)&g_pre[((size_t)t * 1024 + gn) * 64 + b] = acc[ip][j];
        }
    }
}

// ---------------------------------------------------------------------------
// FFMA2 micro-tile: one k-row of one weight matrix into one acc set.
// ---------------------------------------------------------------------------
__device__ __forceinline__ void row_fma(const float* __restrict__ w, int kl, int woff,
                                        u64 hd0, u64 hd1, u64 hd2, u64 hd3,
                                        u64 (&a)[4][4])
{
    const float* wp = w + kl * 16 + woff;
    ulonglong2 w0 = *(const ulonglong2*)wp;
    ulonglong2 w1 = *(const ulonglong2*)(wp + 4);
    ffma2(a[0][0], w0.x, hd0); ffma2(a[0][1], w0.x, hd1);
    ffma2(a[0][2], w0.x, hd2); ffma2(a[0][3], w0.x, hd3);
    ffma2(a[1][0], w0.y, hd0); ffma2(a[1][1], w0.y, hd1);
    ffma2(a[1][2], w0.y, hd2); ffma2(a[1][3], w0.y, hd3);
    ffma2(a[2][0], w1.x, hd0); ffma2(a[2][1], w1.x, hd1);
    ffma2(a[2][2], w1.x, hd2); ffma2(a[2][3], w1.x, hd3);
    ffma2(a[3][0], w1.y, hd0); ffma2(a[3][1], w1.y, hd1);
    ffma2(a[3][2], w1.y, hd2); ffma2(a[3][3], w1.y, hd3);
}

// ---------------------------------------------------------------------------
// Fused main pass: both h sources streamed together, 2-row register prefetch.
// Thread covers 32 k-rows; per row: wt1·h0 -> aA, wt0·h0 -> aB, wt2·h1 -> aA.
// ---------------------------------------------------------------------------
__device__ __forceinline__ void pass_fused(const float* __restrict__ s0,
                                           const float* __restrict__ s1,
                                           const float* __restrict__ w1,
                                           const float* __restrict__ w0,
                                           const float* __restrict__ w2,
                                           u64 (&aA)[4][4], u64 (&aB)[4][4],
                                           int kbase, int hoff, int woff)
{
    const float* p0 = s0 + (size_t)kbase * 64 + hoff;
    const float* p1 = s1 + (size_t)kbase * 64 + hoff;
    float4 f0[2], f1[2];
    f0[0] = __ldcg((const float4*)(p0));
    f1[0] = __ldcg((const float4*)(p1));
    f0[1] = __ldcg((const float4*)(p0 + 64));
    f1[1] = __ldcg((const float4*)(p1 + 64));

    // rows 0..29: unconditional prefetch of row i+2 (max index 31)
    for (int i = 0; i < 30; i += 2) {
#pragma unroll
        for (int u = 0; u < 2; u++) {
            int r = i + u;
            float4 h0v = f0[u], h1v = f1[u];
            f0[u] = __ldcg((const float4*)(p0 + (r + 2) * 64));
            f1[u] = __ldcg((const float4*)(p1 + (r + 2) * 64));
            int kl = kbase + r;
            u64 hd0 = dup2(h0v.x), hd1 = dup2(h0v.y), hd2 = dup2(h0v.z), hd3 = dup2(h0v.w);
            row_fma(w1, kl, woff, hd0, hd1, hd2, hd3, aA);
            row_fma(w0, kl, woff, hd0, hd1, hd2, hd3, aB);
            u64 he0 = dup2(h1v.x), he1 = dup2(h1v.y), he2 = dup2(h1v.z), he3 = dup2(h1v.w);
            row_fma(w2, kl, woff, he0, he1, he2, he3, aA);
        }
    }
    // tail rows 30, 31
#pragma unroll
    for (int u = 0; u < 2; u++) {
        int kl = kbase + 30 + u;
        float4 h0v = f0[u], h1v = f1[u];
        u64 hd0 = dup2(h0v.x), hd1 = dup2(h0v.y), hd2 = dup2(h0v.z), hd3 = dup2(h0v.w);
        row_fma(w1, kl, woff, hd0, hd1, hd2, hd3, aA);
        row_fma(w0, kl, woff, hd0, hd1, hd2, hd3, aB);
        u64 he0 = dup2(h1v.x), he1 = dup2(h1v.y), he2 = dup2(h1v.z), he3 = dup2(h1v.w);
        row_fma(w2, kl, woff, he0, he1, he2, he3, aA);
    }
}

// Single-source pass (prologue only).
__device__ __forceinline__ void pass_one(const float* __restrict__ src,
                                         const float* __restrict__ w,
                                         u64 (&a)[4][4],
                                         int kbase, int hoff, int woff)
{
    const float* p = src + (size_t)kbase * 64 + hoff;
    for (int blk = 0; blk < 4; blk++) {
#pragma unroll
        for (int ii = 0; ii < 8; ii++) {
            int r = blk * 8 + ii;
            float4 h4 = __ldcg((const float4*)(p + r * 64));
            u64 hd0 = dup2(h4.x), hd1 = dup2(h4.y), hd2 = dup2(h4.z), hd3 = dup2(h4.w);
            row_fma(w, kbase + r, woff, hd0, hd1, hd2, hd3, a);
        }
    }
}

// In-warp combine: lane L and L^16 hold identical (j,b) sub-tiles for the two
// 32-row half-granules.
__device__ __forceinline__ void comb(u64 (&a)[4][4])
{
#pragma unroll
    for (int jp = 0; jp < 4; jp++)
#pragma unroll
        for (int bl = 0; bl < 4; bl++) {
            u64 o = __shfl_xor_sync(0xffffffffu, a[jp][bl], 16);
            fadd2(a[jp][bl], o);
        }
}

// Reduction rows padded to 33 u64 to break gather bank conflicts.
__device__ __forceinline__ void stred(u64* red, u64 (&a)[4][4], int gr, int jg, int b0)
{
#pragma unroll
    for (int jp = 0; jp < 4; jp++) {
        int row = gr * 8 + jg * 4 + jp;
#pragma unroll
        for (int bl = 0; bl < 4; bl++)
            red[(size_t)row * 33 + b0 + bl] = a[jp][bl];
    }
}

__device__ __forceinline__ u64 gather16(const u64* red, int jpg, int b)
{
    u64 s0 = red[(size_t)(0 * 8 + jpg) * 33 + b];
    u64 s1 = red[(size_t)(1 * 8 + jpg) * 33 + b];
#pragma unroll
    for (int gr = 2; gr < 16; gr += 2) {
        fadd2(s0, red[(size_t)(gr * 8 + jpg) * 33 + b]);
        fadd2(s1, red[(size_t)((gr + 1) * 8 + jpg) * 33 + b]);
    }
    fadd2(s0, s1);
    return s0;
}

#define ZERO44(A) do { _Pragma("unroll") for (int _j = 0; _j < 4; _j++) \
    _Pragma("unroll") for (int _b = 0; _b < 4; _b++) (A)[_j][_b] = 0ULL; } while (0)

// ---------------------------------------------------------------------------
// Persistent loop. 128 CTAs x 512 thr. CTA = (jt, bh): jt = bid>>1 owns
// j [16*jt, 16*jt+16); bh = bid&1 owns b [32*bh, 32*bh+32).
// Warp w owns k [64w, 64w+64); half-warp k2 covers 32 rows; shuffle-combined
// granule = warp id (16 granules).
// SMEM floats: wt1[0,16K) Wih1 | wt0[16K,32K) Whh0 | wt2[32K,48K) Whh1
//   | red u64[128][33] at 49152 | bias1[57600,+16)   (230,464 B)
// ---------------------------------------------------------------------------
__global__ void __launch_bounds__(NTHR, 1) rnn_persist(
    const float* __restrict__ h0in,
    const float* __restrict__ Whh0, const float* __restrict__ Wih1,
    const float* __restrict__ Whh1, const float* __restrict__ bih1,
    const float* __restrict__ bhh1, float* __restrict__ out)
{
    extern __shared__ float sm[];
    float* wt1 = sm;             // 16384 floats
    float* wt0 = sm + 16384;
    float* wt2 = sm + 32768;
    u64*   red = (u64*)(sm + 49152);   // 128 rows x 33 u64
    float* bias1 = sm + 57600;         // 16

    const int tid  = threadIdx.x;
    const int lane = tid & 31;
    const int warp = tid >> 5;
    const int k2   = lane >> 4;
    const int kbase = warp * 64 + k2 * 32;
    const int jg   = (lane >> 3) & 1;     // j-group (8 j each)
    const int woff = jg * 8;
    const int b0   = (lane & 7) * 4;      // local b 0..28
    const int jt   = blockIdx.x >> 1;
    const int bh   = blockIdx.x & 1;
    const int jbase = jt * 16;
    const int hoff  = bh * 32 + b0;
    // epilogue mapping (tid < 256): 8 j-pairs x 32 b
    const int ejp = tid & 7;
    const int ebl = (tid >> 3) & 31;
    const int ej  = jbase + ejp * 2;
    const int ebg = bh * 32 + ebl;
    u64 tkt = 0;

    // --- prologue: weight slices [k][16] + bias ---
    for (int idx = tid; idx < 16384; idx += NTHR) {
        int jj = idx >> 10, k = idx & 1023;
        wt0[k * 16 + jj] = __ldg(&Whh0[(size_t)(jbase + jj) * 1024 + k]);
        wt1[k * 16 + jj] = __ldg(&Wih1[(size_t)(jbase + jj) * 1024 + k]);
        wt2[k * 16 + jj] = __ldg(&Whh1[(size_t)(jbase + jj) * 1024 + k]);
    }
    if (tid < 16) bias1[tid] = __ldg(&bih1[jbase + tid]) + __ldg(&bhh1[jbase + tid]);

    // --- prologue: transpose h_0 slice (16 k x 32 b x 2 layers = 1024) ---
#pragma unroll
    for (int i = 0; i < 2; i++) {
        int idx = tid + i * NTHR;
        int l = idx >> 9, r = idx & 511;
        int k = jbase + (r >> 5), b = bh * 32 + (r & 31);
        float v = __ldg(&h0in[(size_t)l * 65536 + (size_t)b * 1024 + k]);
        float* dst = l ? g_h1[1] : g_h0[1];
        __stcg(&dst[k * 64 + b], v);
    }
    bar_arrive(tkt);
    bar_wait(tkt);   // init state globally visible

    u64 aA[4][4], aB[4][4];

    // --- prologue: H0[0] = tanh(pre[0] + Whh0·H0[-1]) ---
    ZERO44(aB);
    pass_one(g_h0[1], wt0, aB, kbase, hoff, woff);
    comb(aB);
    if (lane < 16) stred(red, aB, warp, jg, b0);
    __syncthreads();
    if (tid < 256) {
        u64 v = gather16(red, ejp, ebl);
        float lo, hi; unpack2(v, lo, hi);
        const float* pp = g_pre + (size_t)ej * 64 + ebg;
        __stcg(&g_h0[0][ej * 64 + ebg], tanhf(lo + __ldcg(pp)));
        __stcg(&g_h0[0][(ej + 1) * 64 + ebg], tanhf(hi + __ldcg(pp + 64)));
    }
    bar_arrive(tkt);

    // --- main loop: interval t computes H1[t] (aA) and H0[t+1] (aB) ---
    for (int t = 0; t < TT; t++) {
        const int p = t & 1;

        // prefetch pre[t+1] while other CTAs reach the barrier
        float pf0 = 0.f, pf1 = 0.f;
        if (t < TT - 1 && tid < 256) {
            const float* pp = g_pre + ((size_t)(t + 1) * 1024 + ej) * 64 + ebg;
            pf0 = __ldcg(pp);
            pf1 = __ldcg(pp + 64);
        }
        bar_wait(tkt);   // H0[t], H1[t-1] from all CTAs visible

        ZERO44(aA); ZERO44(aB);
        pass_fused(g_h0[p], g_h1[p ^ 1], wt1, wt0, wt2, aA, aB, kbase, hoff, woff);
        comb(aA);
        comb(aB);

        // round 1: H1[t] from aA
        __syncthreads();   // prior gather reads of red are done
        if (lane < 16) stred(red, aA, warp, jg, b0);
        __syncthreads();
        if (tid < 256) {
            u64 v = gather16(red, ejp, ebl);
            float lo, hi; unpack2(v, lo, hi);
            float v0 = tanhf(lo + bias1[ejp * 2]);
            float v1 = tanhf(hi + bias1[ejp * 2 + 1]);
            __stcg(&g_h1[p][ej * 64 + ebg], v0);
            __stcg(&g_h1[p][(ej + 1) * 64 + ebg], v1);
            float2 ov; ov.x = v0; ov.y = v1;
            *(float2*)&out[(size_t)t * 65536 + (size_t)ebg * 1024 + ej] = ov;
        }

        // round 2: H0[t+1] from aB
        if (t < TT - 1) {
            __syncthreads();
            if (lane < 16) stred(red, aB, warp, jg, b0);
            __syncthreads();
            if (tid < 256) {
                u64 v = gather16(red, ejp, ebl);
                float lo, hi; unpack2(v, lo, hi);
                __stcg(&g_h0[p ^ 1][ej * 64 + ebg], tanhf(lo + pf0));
                __stcg(&g_h0[p ^ 1][(ej + 1) * 64 + ebg], tanhf(hi + pf1));
            }
        }
        bar_arrive(tkt);   // includes __syncthreads (protects red for next step)
    }
    bar_wait(tkt);   // all final states visible

    // h_n: H0[511] in g_h0[1], H1[511] in g_h1[1]
    for (int e = blockIdx.x * NTHR + tid; e < 2 * BB * HH; e += NCTA * NTHR) {
        int l = e >> 16, r = e & 65535, b = r >> 10, k = r & 1023;
        const float* src = l ? g_h1[1] : g_h0[1];
        out[(size_t)TT * BB * HH + e] = __ldcg(&src[k * 64 + b]);
    }
}

// ---------------------------------------------------------------------------
extern "C" void kernel_launch(void* const* d_in, const int* in_sizes, int n_in,
                              void* d_out, int out_size)
{
    const float* input = (const float*)d_in[0];
    const float* h0in  = (const float*)d_in[1];
    const float* Wih0  = (const float*)d_in[2];
    const float* bih0  = (const float*)d_in[3];
    const float* Whh0  = (const float*)d_in[4];
    const float* bhh0  = (const float*)d_in[5];
    const float* Wih1  = (const float*)d_in[6];
    const float* bih1  = (const float*)d_in[7];
    const float* Whh1  = (const float*)d_in[8];
    const float* bhh1  = (const float*)d_in[9];
    float* out = (float*)d_out;

    const int smem_bytes = 230464;
    cudaFuncSetAttribute(rnn_persist, cudaFuncAttributeMaxDynamicSharedMemorySize, smem_bytes);

    pregemm<<<dim3(16, 256), 256>>>(input, Wih0, bih0, bhh0);
    rnn_persist<<<NCTA, NTHR, smem_bytes>>>(h0in, Whh0, Wih1, Whh1, bih1, bhh1, out);
}

// round 16
// speedup vs baseline: 1.0408x; 1.0408x over previous
#include <cuda_runtime.h>
#include <math.h>
#include <stdint.h>

#define TT 512
#define BB 64
#define HH 1024
#define NCTA 128
#define NTHR 512

typedef unsigned long long u64;

__device__ __align__(256) float g_pre[(size_t)TT * HH * BB];  // [t][j][b]
__device__ __align__(256) float g_h0[2][HH * BB];             // [k][b]; H0[t] in g_h0[t&1]
__device__ __align__(256) float g_h1[2][HH * BB];             // H1[t] in g_h1[t&1]
__device__ __align__(128) u64 g_flags[NCTA * 16];             // per-CTA barrier flags, 128B apart

__device__ __forceinline__ void ffma2(u64& d, u64 a, u64 b)
{ asm("fma.rn.f32x2 %0,%1,%2,%0;" : "+l"(d) : "l"(a), "l"(b)); }
__device__ __forceinline__ void fadd2(u64& d, u64 a)
{ asm("add.rn.f32x2 %0,%0,%1;" : "+l"(d) : "l"(a)); }
__device__ __forceinline__ u64 dup2(float x)
{ u64 r; asm("mov.b64 %0,{%1,%1};" : "=l"(r) : "f"(x)); return r; }
__device__ __forceinline__ void unpack2(u64 s, float& lo, float& hi)
{ asm("mov.b64 {%0,%1},%2;" : "=f"(lo), "=f"(hi) : "l"(s)); }

// ---------------------------------------------------------------------------
// Distributed flag barrier. Each CTA owns one 128B-spaced u64 slot. Arrive =
// bump own slot (no atomics, no serialization). Wait = threads 0..127 each
// spin on one CTA's slot. Generations are monotonic per-CTA counters; every
// CTA does the same number of arrivals per launch and seeds from its OWN slot
// at kernel start, so the scheme is correct across graph replays.
// ---------------------------------------------------------------------------
__device__ __forceinline__ void bar_arrive(u64& tkt)
{
    tkt += 1;
    __syncthreads();
    if (threadIdx.x == 0) {
        __threadfence();
        *(volatile u64*)&g_flags[blockIdx.x * 16] = tkt;
    }
}
__device__ __forceinline__ void bar_wait(u64 tkt)
{
    if (threadIdx.x < NCTA) {
        while (*(volatile u64*)&g_flags[threadIdx.x * 16] < tkt) {}
        __threadfence();
    }
    __syncthreads();
}

// ---------------------------------------------------------------------------
// pregemm (FFMA2): g_pre[t][j][b] = x[t][b]·Wih0[j] + bih0[j] + bhh0[j]
// ---------------------------------------------------------------------------
__global__ void __launch_bounds__(256) pregemm(const float* __restrict__ X,
                                               const float* __restrict__ W,
                                               const float* __restrict__ bih,
                                               const float* __restrict__ bhh)
{
    __shared__ float As[16][132];  // [k][m]
    __shared__ float Bs[16][68];   // [k][n]
    const int tid = threadIdx.x;
    const int m0 = blockIdx.y * 128;
    const int n0 = blockIdx.x * 64;
    const int tx = tid & 15;
    const int ty = tid >> 4;

    u64 acc[4][4];
#pragma unroll
    for (int i = 0; i < 4; i++)
#pragma unroll
        for (int j = 0; j < 4; j++) acc[i][j] = 0ULL;

    for (int k0 = 0; k0 < 1024; k0 += 16) {
#pragma unroll
        for (int i = 0; i < 2; i++) {
            int q = tid + i * 256;
            int m = q >> 2, kq = (q & 3) << 2;
            float4 v = __ldg((const float4*)&X[(size_t)(m0 + m) * 1024 + k0 + kq]);
            As[kq + 0][m] = v.x; As[kq + 1][m] = v.y;
            As[kq + 2][m] = v.z; As[kq + 3][m] = v.w;
        }
        {
            int n = tid >> 2, kq = (tid & 3) << 2;
            float4 v = __ldg((const float4*)&W[(size_t)(n0 + n) * 1024 + k0 + kq]);
            Bs[kq + 0][n] = v.x; Bs[kq + 1][n] = v.y;
            Bs[kq + 2][n] = v.z; Bs[kq + 3][n] = v.w;
        }
        __syncthreads();
#pragma unroll
        for (int kk = 0; kk < 16; kk++) {
            ulonglong2 a01 = *(const ulonglong2*)&As[kk][ty * 8];
            ulonglong2 a23 = *(const ulonglong2*)&As[kk][ty * 8 + 4];
            float4 bv = *(const float4*)&Bs[kk][tx * 4];
            u64 bd0 = dup2(bv.x), bd1 = dup2(bv.y), bd2 = dup2(bv.z), bd3 = dup2(bv.w);
            ffma2(acc[0][0], a01.x, bd0); ffma2(acc[0][1], a01.x, bd1);
            ffma2(acc[0][2], a01.x, bd2); ffma2(acc[0][3], a01.x, bd3);
            ffma2(acc[1][0], a01.y, bd0); ffma2(acc[1][1], a01.y, bd1);
            ffma2(acc[1][2], a01.y, bd2); ffma2(acc[1][3], a01.y, bd3);
            ffma2(acc[2][0], a23.x, bd0); ffma2(acc[2][1], a23.x, bd1);
            ffma2(acc[2][2], a23.x, bd2); ffma2(acc[2][3], a23.x, bd3);
            ffma2(acc[3][0], a23.y, bd0); ffma2(acc[3][1], a23.y, bd1);
            ffma2(acc[3][2], a23.y, bd2); ffma2(acc[3][3], a23.y, bd3);
        }
        __syncthreads();
    }

#pragma unroll
    for (int ip = 0; ip < 4; ip++) {
        int m = m0 + ty * 8 + 2 * ip;
        int t = m >> 6, b = m & 63;
#pragma unroll
        for (int j = 0; j < 4; j++) {
            int gn = n0 + tx * 4 + j;
            u64 bias = dup2(__ldg(&bih[gn]) + __ldg(&bhh[gn]));
            fadd2(acc[ip][j], bias);
            *(u64*)&g_pre[((size_t)t * 1024 + gn) * 64 + b] = acc[ip][j];
        }
    }
}

// ---------------------------------------------------------------------------
// FFMA2 micro-tile: one k-row of one weight matrix into one acc set.
// ---------------------------------------------------------------------------
__device__ __forceinline__ void row_fma(const float* __restrict__ w, int kl, int woff,
                                        u64 hd0, u64 hd1, u64 hd2, u64 hd3,
                                        u64 (&a)[4][4])
{
    const float* wp = w + kl * 16 + woff;
    ulonglong2 w0 = *(const ulonglong2*)wp;
    ulonglong2 w1 = *(const ulonglong2*)(wp + 4);
    ffma2(a[0][0], w0.x, hd0); ffma2(a[0][1], w0.x, hd1);
    ffma2(a[0][2], w0.x, hd2); ffma2(a[0][3], w0.x, hd3);
    ffma2(a[1][0], w0.y, hd0); ffma2(a[1][1], w0.y, hd1);
    ffma2(a[1][2], w0.y, hd2); ffma2(a[1][3], w0.y, hd3);
    ffma2(a[2][0], w1.x, hd0); ffma2(a[2][1], w1.x, hd1);
    ffma2(a[2][2], w1.x, hd2); ffma2(a[2][3], w1.x, hd3);
    ffma2(a[3][0], w1.y, hd0); ffma2(a[3][1], w1.y, hd1);
    ffma2(a[3][2], w1.y, hd2); ffma2(a[3][3], w1.y, hd3);
}

// ---------------------------------------------------------------------------
// Fused main pass: both h sources streamed together, 2-row register prefetch.
// Thread covers 32 k-rows; per row: wt1·h0 -> aA, wt0·h0 -> aB, wt2·h1 -> aA.
// ---------------------------------------------------------------------------
__device__ __forceinline__ void pass_fused(const float* __restrict__ s0,
                                           const float* __restrict__ s1,
                                           const float* __restrict__ w1,
                                           const float* __restrict__ w0,
                                           const float* __restrict__ w2,
                                           u64 (&aA)[4][4], u64 (&aB)[4][4],
                                           int kbase, int hoff, int woff)
{
    const float* p0 = s0 + (size_t)kbase * 64 + hoff;
    const float* p1 = s1 + (size_t)kbase * 64 + hoff;
    float4 f0[2], f1[2];
    f0[0] = __ldcg((const float4*)(p0));
    f1[0] = __ldcg((const float4*)(p1));
    f0[1] = __ldcg((const float4*)(p0 + 64));
    f1[1] = __ldcg((const float4*)(p1 + 64));

    // rows 0..29: unconditional prefetch of row i+2 (max index 31)
    for (int i = 0; i < 30; i += 2) {
#pragma unroll
        for (int u = 0; u < 2; u++) {
            int r = i + u;
            float4 h0v = f0[u], h1v = f1[u];
            f0[u] = __ldcg((const float4*)(p0 + (r + 2) * 64));
            f1[u] = __ldcg((const float4*)(p1 + (r + 2) * 64));
            int kl = kbase + r;
            u64 hd0 = dup2(h0v.x), hd1 = dup2(h0v.y), hd2 = dup2(h0v.z), hd3 = dup2(h0v.w);
            row_fma(w1, kl, woff, hd0, hd1, hd2, hd3, aA);
            row_fma(w0, kl, woff, hd0, hd1, hd2, hd3, aB);
            u64 he0 = dup2(h1v.x), he1 = dup2(h1v.y), he2 = dup2(h1v.z), he3 = dup2(h1v.w);
            row_fma(w2, kl, woff, he0, he1, he2, he3, aA);
        }
    }
    // tail rows 30, 31
#pragma unroll
    for (int u = 0; u < 2; u++) {
        int kl = kbase + 30 + u;
        float4 h0v = f0[u], h1v = f1[u];
        u64 hd0 = dup2(h0v.x), hd1 = dup2(h0v.y), hd2 = dup2(h0v.z), hd3 = dup2(h0v.w);
        row_fma(w1, kl, woff, hd0, hd1, hd2, hd3, aA);
        row_fma(w0, kl, woff, hd0, hd1, hd2, hd3, aB);
        u64 he0 = dup2(h1v.x), he1 = dup2(h1v.y), he2 = dup2(h1v.z), he3 = dup2(h1v.w);
        row_fma(w2, kl, woff, he0, he1, he2, he3, aA);
    }
}

// Single-source pass (prologue only).
__device__ __forceinline__ void pass_one(const float* __restrict__ src,
                                         const float* __restrict__ w,
                                         u64 (&a)[4][4],
                                         int kbase, int hoff, int woff)
{
    const float* p = src + (size_t)kbase * 64 + hoff;
    for (int blk = 0; blk < 4; blk++) {
#pragma unroll
        for (int ii = 0; ii < 8; ii++) {
            int r = blk * 8 + ii;
            float4 h4 = __ldcg((const float4*)(p + r * 64));
            u64 hd0 = dup2(h4.x), hd1 = dup2(h4.y), hd2 = dup2(h4.z), hd3 = dup2(h4.w);
            row_fma(w, kbase + r, woff, hd0, hd1, hd2, hd3, a);
        }
    }
}

// In-warp combine: lane L and L^16 hold identical (j,b) sub-tiles for the two
// 32-row half-granules.
__device__ __forceinline__ void comb(u64 (&a)[4][4])
{
#pragma unroll
    for (int jp = 0; jp < 4; jp++)
#pragma unroll
        for (int bl = 0; bl < 4; bl++) {
            u64 o = __shfl_xor_sync(0xffffffffu, a[jp][bl], 16);
            fadd2(a[jp][bl], o);
        }
}

// Reduction rows padded to 33 u64 to break gather bank conflicts.
__device__ __forceinline__ void stred(u64* red, u64 (&a)[4][4], int gr, int jg, int b0)
{
#pragma unroll
    for (int jp = 0; jp < 4; jp++) {
        int row = gr * 8 + jg * 4 + jp;
#pragma unroll
        for (int bl = 0; bl < 4; bl++)
            red[(size_t)row * 33 + b0 + bl] = a[jp][bl];
    }
}

__device__ __forceinline__ u64 gather16(const u64* red, int jpg, int b)
{
    u64 s0 = red[(size_t)(0 * 8 + jpg) * 33 + b];
    u64 s1 = red[(size_t)(1 * 8 + jpg) * 33 + b];
#pragma unroll
    for (int gr = 2; gr < 16; gr += 2) {
        fadd2(s0, red[(size_t)(gr * 8 + jpg) * 33 + b]);
        fadd2(s1, red[(size_t)((gr + 1) * 8 + jpg) * 33 + b]);
    }
    fadd2(s0, s1);
    return s0;
}

#define ZERO44(A) do { _Pragma("unroll") for (int _j = 0; _j < 4; _j++) \
    _Pragma("unroll") for (int _b = 0; _b < 4; _b++) (A)[_j][_b] = 0ULL; } while (0)

// ---------------------------------------------------------------------------
// Persistent loop. 128 CTAs x 512 thr. CTA = (jt, bh): jt = bid>>1 owns
// j [16*jt, 16*jt+16); bh = bid&1 owns b [32*bh, 32*bh+32).
// Warp w owns k [64w, 64w+64); half-warp k2 covers 32 rows; shuffle-combined
// granule = warp id (16 granules).
// SMEM floats: wt1[0,16K) Wih1 | wt0[16K,32K) Whh0 | wt2[32K,48K) Whh1
//   | red u64[128][33] at 49152 | bias1[57600,+16)   (230,464 B)
// ---------------------------------------------------------------------------
__global__ void __launch_bounds__(NTHR, 1) rnn_persist(
    const float* __restrict__ h0in,
    const float* __restrict__ Whh0, const float* __restrict__ Wih1,
    const float* __restrict__ Whh1, const float* __restrict__ bih1,
    const float* __restrict__ bhh1, float* __restrict__ out)
{
    extern __shared__ float sm[];
    float* wt1 = sm;             // 16384 floats
    float* wt0 = sm + 16384;
    float* wt2 = sm + 32768;
    u64*   red = (u64*)(sm + 49152);   // 128 rows x 33 u64
    float* bias1 = sm + 57600;         // 16

    const int tid  = threadIdx.x;
    const int lane = tid & 31;
    const int warp = tid >> 5;
    const int k2   = lane >> 4;
    const int kbase = warp * 64 + k2 * 32;
    const int jg   = (lane >> 3) & 1;     // j-group (8 j each)
    const int woff = jg * 8;
    const int b0   = (lane & 7) * 4;      // local b 0..28
    const int jt   = blockIdx.x >> 1;
    const int bh   = blockIdx.x & 1;
    const int jbase = jt * 16;
    const int hoff  = bh * 32 + b0;
    // epilogue mapping (tid < 256): 8 j-pairs x 32 b
    const int ejp = tid & 7;
    const int ebl = (tid >> 3) & 31;
    const int ej  = jbase + ejp * 2;
    const int ebg = bh * 32 + ebl;

    // seed barrier generation from OWN flag (replay-safe; all slots equal here)
    u64 tkt = *(volatile u64*)&g_flags[blockIdx.x * 16];

    // --- prologue: weight slices [k][16] + bias ---
    for (int idx = tid; idx < 16384; idx += NTHR) {
        int jj = idx >> 10, k = idx & 1023;
        wt0[k * 16 + jj] = __ldg(&Whh0[(size_t)(jbase + jj) * 1024 + k]);
        wt1[k * 16 + jj] = __ldg(&Wih1[(size_t)(jbase + jj) * 1024 + k]);
        wt2[k * 16 + jj] = __ldg(&Whh1[(size_t)(jbase + jj) * 1024 + k]);
    }
    if (tid < 16) bias1[tid] = __ldg(&bih1[jbase + tid]) + __ldg(&bhh1[jbase + tid]);

    // --- prologue: transpose h_0 slice (16 k x 32 b x 2 layers = 1024) ---
#pragma unroll
    for (int i = 0; i < 2; i++) {
        int idx = tid + i * NTHR;
        int l = idx >> 9, r = idx & 511;
        int k = jbase + (r >> 5), b = bh * 32 + (r & 31);
        float v = __ldg(&h0in[(size_t)l * 65536 + (size_t)b * 1024 + k]);
        float* dst = l ? g_h1[1] : g_h0[1];
        __stcg(&dst[k * 64 + b], v);
    }
    bar_arrive(tkt);
    bar_wait(tkt);   // init state globally visible

    u64 aA[4][4], aB[4][4];

    // --- prologue: H0[0] = tanh(pre[0] + Whh0·H0[-1]) ---
    ZERO44(aB);
    pass_one(g_h0[1], wt0, aB, kbase, hoff, woff);
    comb(aB);
    if (lane < 16) stred(red, aB, warp, jg, b0);
    __syncthreads();
    if (tid < 256) {
        u64 v = gather16(red, ejp, ebl);
        float lo, hi; unpack2(v, lo, hi);
        const float* pp = g_pre + (size_t)ej * 64 + ebg;
        __stcg(&g_h0[0][ej * 64 + ebg], tanhf(lo + __ldcg(pp)));
        __stcg(&g_h0[0][(ej + 1) * 64 + ebg], tanhf(hi + __ldcg(pp + 64)));
    }
    bar_arrive(tkt);

    // --- main loop: interval t computes H1[t] (aA) and H0[t+1] (aB) ---
    for (int t = 0; t < TT; t++) {
        const int p = t & 1;

        // prefetch pre[t+1] while other CTAs reach the barrier
        float pf0 = 0.f, pf1 = 0.f;
        if (t < TT - 1 && tid < 256) {
            const float* pp = g_pre + ((size_t)(t + 1) * 1024 + ej) * 64 + ebg;
            pf0 = __ldcg(pp);
            pf1 = __ldcg(pp + 64);
        }
        bar_wait(tkt);   // H0[t], H1[t-1] from all CTAs visible

        ZERO44(aA); ZERO44(aB);
        pass_fused(g_h0[p], g_h1[p ^ 1], wt1, wt0, wt2, aA, aB, kbase, hoff, woff);
        comb(aA);
        comb(aB);

        // round 1: H1[t] from aA  (red protected by bar_arrive/bar_wait syncs)
        if (lane < 16) stred(red, aA, warp, jg, b0);
        __syncthreads();
        if (tid < 256) {
            u64 v = gather16(red, ejp, ebl);
            float lo, hi; unpack2(v, lo, hi);
            float v0 = tanhf(lo + bias1[ejp * 2]);
            float v1 = tanhf(hi + bias1[ejp * 2 + 1]);
            __stcg(&g_h1[p][ej * 64 + ebg], v0);
            __stcg(&g_h1[p][(ej + 1) * 64 + ebg], v1);
            float2 ov; ov.x = v0; ov.y = v1;
            *(float2*)&out[(size_t)t * 65536 + (size_t)ebg * 1024 + ej] = ov;
        }

        // round 2: H0[t+1] from aB
        if (t < TT - 1) {
            __syncthreads();
            if (lane < 16) stred(red, aB, warp, jg, b0);
            __syncthreads();
            if (tid < 256) {
                u64 v = gather16(red, ejp, ebl);
                float lo, hi; unpack2(v, lo, hi);
                __stcg(&g_h0[p ^ 1][ej * 64 + ebg], tanhf(lo + pf0));
                __stcg(&g_h0[p ^ 1][(ej + 1) * 64 + ebg], tanhf(hi + pf1));
            }
        }
        bar_arrive(tkt);   // includes __syncthreads (protects red for next step)
    }
    bar_wait(tkt);   // all final states visible

    // h_n: H0[511] in g_h0[1], H1[511] in g_h1[1]
    for (int e = blockIdx.x * NTHR + tid; e < 2 * BB * HH; e += NCTA * NTHR) {
        int l = e >> 16, r = e & 65535, b = r >> 10, k = r & 1023;
        const float* src = l ? g_h1[1] : g_h0[1];
        out[(size_t)TT * BB * HH + e] = __ldcg(&src[k * 64 + b]);
    }
}

// ---------------------------------------------------------------------------
extern "C" void kernel_launch(void* const* d_in, const int* in_sizes, int n_in,
                              void* d_out, int out_size)
{
    const float* input = (const float*)d_in[0];
    const float* h0in  = (const float*)d_in[1];
    const float* Wih0  = (const float*)d_in[2];
    const float* bih0  = (const float*)d_in[3];
    const float* Whh0  = (const float*)d_in[4];
    const float* bhh0  = (const float*)d_in[5];
    const float* Wih1  = (const float*)d_in[6];
    const float* bih1  = (const float*)d_in[7];
    const float* Whh1  = (const float*)d_in[8];
    const float* bhh1  = (const float*)d_in[9];
    float* out = (float*)d_out;

    const int smem_bytes = 230464;
    cudaFuncSetAttribute(rnn_persist, cudaFuncAttributeMaxDynamicSharedMemorySize, smem_bytes);

    pregemm<<<dim3(16, 256), 256>>>(input, Wih0, bih0, bhh0);
    rnn_persist<<<NCTA, NTHR, smem_bytes>>>(h0in, Whh0, Wih1, Whh1, bih1, bhh1, out);
}